// round 1
// baseline (speedup 1.0000x reference)
#include <cuda_runtime.h>
#include <cuda_bf16.h>
#include <math.h>

// Problem constants (fixed by the dataset's setup_inputs)
constexpr int B_  = 8;
constexpr int Q_  = 2048;
constexpr int D_  = 256;
constexpr int Hh  = 100;
constexpr int Ww  = 100;
constexpr int HW  = Hh * Ww;       // 10000
constexpr int NH  = 8;
constexpr int NP  = 4;
constexpr int DH  = D_ / NH;       // 32

// Scratch (allocation-free rule: __device__ globals)
__device__ float g_values[(size_t)B_ * HW * D_];   // 81.9 MB
__device__ float g_result[(size_t)B_ * Q_ * D_];   // 16.8 MB

// ---------------------------------------------------------------------------
// SGEMM: C[M,N] = A[M,K] * W[K,N] + bias[N]   (row-major, K=256, exact tiles)
// BM=128, BN=128, BK=8, 256 threads, 8x8 per thread.
// ---------------------------------------------------------------------------
constexpr int BM = 128, BN = 128, BK = 8, TM = 8, TN = 8;
constexpr int APAD = 4;  // As row stride = BM + 4 = 132 (float4-aligned, conflict-free)

__global__ __launch_bounds__(256, 2)
void sgemm_bias_kernel(const float* __restrict__ A,
                       const float* __restrict__ W,
                       const float* __restrict__ bias,
                       float* __restrict__ C,
                       int M, int N, int K)
{
    __shared__ float As[BK * (BM + APAD)];
    __shared__ float Bs[BK * BN];

    const int bm = blockIdx.y * BM;
    const int bn = blockIdx.x * BN;
    const int tid = threadIdx.x;

    const int tx = tid % (BN / TN);   // 0..15
    const int ty = tid / (BN / TN);   // 0..15

    // A-tile load mapping: 128 rows x 8 cols -> 256 float4 loads
    const int arow  = tid >> 1;          // 0..127
    const int acol4 = (tid & 1) * 4;     // 0 or 4
    // B-tile load mapping: 8 rows x 128 cols
    const int brow  = tid >> 5;          // 0..7
    const int bcol  = (tid & 31) * 4;    // 0..124

    float acc[TM][TN];
    #pragma unroll
    for (int i = 0; i < TM; i++)
        #pragma unroll
        for (int j = 0; j < TN; j++) acc[i][j] = 0.f;

    const float* Ab = A + (size_t)bm * K;

    for (int k0 = 0; k0 < K; k0 += BK) {
        float4 a4 = *(const float4*)(Ab + (size_t)arow * K + k0 + acol4);
        As[(acol4 + 0) * (BM + APAD) + arow] = a4.x;
        As[(acol4 + 1) * (BM + APAD) + arow] = a4.y;
        As[(acol4 + 2) * (BM + APAD) + arow] = a4.z;
        As[(acol4 + 3) * (BM + APAD) + arow] = a4.w;

        float4 b4 = *(const float4*)(W + (size_t)(k0 + brow) * N + bn + bcol);
        *(float4*)(&Bs[brow * BN + bcol]) = b4;

        __syncthreads();

        #pragma unroll
        for (int k = 0; k < BK; k++) {
            float ra[TM], rb[TN];
            #pragma unroll
            for (int i = 0; i < TM; i += 4)
                *(float4*)(&ra[i]) = *(const float4*)(&As[k * (BM + APAD) + ty * TM + i]);
            #pragma unroll
            for (int j = 0; j < TN; j += 4)
                *(float4*)(&rb[j]) = *(const float4*)(&Bs[k * BN + tx * TN + j]);
            #pragma unroll
            for (int i = 0; i < TM; i++)
                #pragma unroll
                for (int j = 0; j < TN; j++)
                    acc[i][j] = fmaf(ra[i], rb[j], acc[i][j]);
        }
        __syncthreads();
    }

    float bs[TN];
    #pragma unroll
    for (int j = 0; j < TN; j++) bs[j] = bias[bn + tx * TN + j];

    #pragma unroll
    for (int i = 0; i < TM; i++) {
        float* crow = C + (size_t)(bm + ty * TM + i) * N + bn + tx * TN;
        #pragma unroll
        for (int j = 0; j < TN; j += 4) {
            float4 v;
            v.x = acc[i][j + 0] + bs[j + 0];
            v.y = acc[i][j + 1] + bs[j + 1];
            v.z = acc[i][j + 2] + bs[j + 2];
            v.w = acc[i][j + 3] + bs[j + 3];
            *(float4*)(crow + j) = v;
        }
    }
}

// ---------------------------------------------------------------------------
// Fused: offset/attn projection + softmax + bilinear gather.
// One CTA of 256 threads per (b,q). Warp h handles head h, lane = Dh channel.
// ---------------------------------------------------------------------------
__global__ __launch_bounds__(256)
void sample_kernel(const float* __restrict__ query,
                   const float* __restrict__ refpts,
                   const float* __restrict__ W_off,
                   const float* __restrict__ b_off,
                   const float* __restrict__ W_attn,
                   const float* __restrict__ b_attn)
{
    const int bq = blockIdx.x;          // 0..B*Q-1
    const int b  = bq / Q_;
    const int t  = threadIdx.x;

    __shared__ float qs[D_];
    __shared__ float offs[NH * NP * 2];   // 64
    __shared__ float attn[NH * NP];       // 32

    qs[t] = query[(size_t)bq * D_ + t];
    __syncthreads();

    // Projections: 96 dot products of length 256
    if (t < 64) {
        const float* W = W_off + t;
        float s0 = 0.f, s1 = 0.f, s2 = 0.f, s3 = 0.f;
        #pragma unroll 8
        for (int k = 0; k < D_; k += 4) {
            s0 = fmaf(qs[k + 0], W[(k + 0) * 64], s0);
            s1 = fmaf(qs[k + 1], W[(k + 1) * 64], s1);
            s2 = fmaf(qs[k + 2], W[(k + 2) * 64], s2);
            s3 = fmaf(qs[k + 3], W[(k + 3) * 64], s3);
        }
        offs[t] = (s0 + s1) + (s2 + s3) + b_off[t];
    } else if (t < 96) {
        const int j = t - 64;
        const float* W = W_attn + j;
        float s0 = 0.f, s1 = 0.f, s2 = 0.f, s3 = 0.f;
        #pragma unroll 8
        for (int k = 0; k < D_; k += 4) {
            s0 = fmaf(qs[k + 0], W[(k + 0) * 32], s0);
            s1 = fmaf(qs[k + 1], W[(k + 1) * 32], s1);
            s2 = fmaf(qs[k + 2], W[(k + 2) * 32], s2);
            s3 = fmaf(qs[k + 3], W[(k + 3) * 32], s3);
        }
        attn[j] = (s0 + s1) + (s2 + s3) + b_attn[j];
    }
    __syncthreads();

    // Softmax over the NP points of each head
    if (t < NH) {
        float m = attn[t * NP];
        #pragma unroll
        for (int p = 1; p < NP; p++) m = fmaxf(m, attn[t * NP + p]);
        float e[NP], s = 0.f;
        #pragma unroll
        for (int p = 0; p < NP; p++) { e[p] = __expf(attn[t * NP + p] - m); s += e[p]; }
        float inv = 1.f / s;
        #pragma unroll
        for (int p = 0; p < NP; p++) attn[t * NP + p] = e[p] * inv;
    }
    __syncthreads();

    // Bilinear sampling: warp h = head h, lane d = channel
    const int h = t >> 5;
    const int d = t & 31;
    const float rx = refpts[(size_t)bq * 2 + 0];
    const float ry = refpts[(size_t)bq * 2 + 1];
    const float* vb = g_values + (size_t)b * HW * D_ + h * DH + d;

    float acc = 0.f;
    #pragma unroll
    for (int p = 0; p < NP; p++) {
        float lx = fminf(fmaxf(rx + offs[(h * NP + p) * 2 + 0], 0.f), 1.f);
        float ly = fminf(fmaxf(ry + offs[(h * NP + p) * 2 + 1], 0.f), 1.f);
        float sx = lx * (float)(Ww - 1);
        float sy = ly * (float)(Hh - 1);
        int x0 = min(max((int)floorf(sx), 0), Ww - 1);
        int y0 = min(max((int)floorf(sy), 0), Hh - 1);
        int x1 = min(x0 + 1, Ww - 1);
        int y1 = min(y0 + 1, Hh - 1);
        float wx1 = sx - (float)x0, wx0 = 1.f - wx1;
        float wy1 = sy - (float)y0, wy0 = 1.f - wy1;

        float g00 = vb[(size_t)(y0 * Ww + x0) * D_];
        float g01 = vb[(size_t)(y1 * Ww + x0) * D_];
        float g10 = vb[(size_t)(y0 * Ww + x1) * D_];
        float g11 = vb[(size_t)(y1 * Ww + x1) * D_];

        float bil = g00 * (wx0 * wy0) + g01 * (wx0 * wy1)
                  + g10 * (wx1 * wy0) + g11 * (wx1 * wy1);
        acc = fmaf(attn[h * NP + p], bil, acc);
    }
    g_result[(size_t)bq * D_ + t] = acc;
}

// ---------------------------------------------------------------------------
// kernel_launch
// Inputs (metadata order): 0=query 1=reference_points 2=input_flatten 3=h 4=w
//   5=W_off 6=b_off 7=W_attn 8=b_attn 9=W_val 10=b_val 11=W_out 12=b_out
// ---------------------------------------------------------------------------
extern "C" void kernel_launch(void* const* d_in, const int* in_sizes, int n_in,
                              void* d_out, int out_size)
{
    const float* query    = (const float*)d_in[0];
    const float* refpts   = (const float*)d_in[1];
    const float* in_flat  = (const float*)d_in[2];
    const float* W_off    = (const float*)d_in[5];
    const float* b_off    = (const float*)d_in[6];
    const float* W_attn   = (const float*)d_in[7];
    const float* b_attn   = (const float*)d_in[8];
    const float* W_val    = (const float*)d_in[9];
    const float* b_val    = (const float*)d_in[10];
    const float* W_out    = (const float*)d_in[11];
    const float* b_out    = (const float*)d_in[12];
    float* out = (float*)d_out;

    float* values_ptr;
    float* result_ptr;
    cudaGetSymbolAddress((void**)&values_ptr, g_values);
    cudaGetSymbolAddress((void**)&result_ptr, g_result);

    // 1) values = input_flatten @ W_val + b_val   [B*HW, 256]
    {
        dim3 grid(D_ / BN, (B_ * HW) / BM);   // (2, 625)
        sgemm_bias_kernel<<<grid, 256>>>(in_flat, W_val, b_val, values_ptr,
                                         B_ * HW, D_, D_);
    }

    // 2) fused projection + softmax + bilinear sampling -> g_result [B*Q, 256]
    sample_kernel<<<B_ * Q_, 256>>>(query, refpts, W_off, b_off, W_attn, b_attn);

    // 3) out = result @ W_out + b_out   [B*Q, 256]
    {
        dim3 grid(D_ / BN, (B_ * Q_) / BM);   // (2, 128)
        sgemm_bias_kernel<<<grid, 256>>>(result_ptr, W_out, b_out, out,
                                         B_ * Q_, D_, D_);
    }
}

// round 5
// speedup vs baseline: 1.8774x; 1.8774x over previous
#include <cuda_runtime.h>
#include <cuda_bf16.h>
#include <math.h>
#include <cstdint>

// ---------------------------------------------------------------------------
// Problem constants (fixed by the dataset's setup_inputs)
// ---------------------------------------------------------------------------
constexpr int B_  = 8;
constexpr int Q_  = 2048;
constexpr int D_  = 256;
constexpr int Hh  = 100;
constexpr int Ww  = 100;
constexpr int HW  = Hh * Ww;       // 10000
constexpr int NH  = 8;
constexpr int NP  = 4;
constexpr int DH  = D_ / NH;       // 32
constexpr int BQ  = B_ * Q_;       // 16384
constexpr int PN  = 128;           // padded projection width (64 off + 32 attn + pad)

// Scratch (allocation-free rule: __device__ globals)
__device__ float         g_values[(size_t)B_ * HW * D_];   // 81.9 MB
__device__ float         g_result[(size_t)BQ * D_];        // 16.8 MB
__device__ float         g_proj[(size_t)BQ * PN];          // 8.4 MB
__device__ __nv_bfloat16 g_WvalT_hi[D_ * D_], g_WvalT_lo[D_ * D_];
__device__ __nv_bfloat16 g_WoutT_hi[D_ * D_], g_WoutT_lo[D_ * D_];
__device__ __nv_bfloat16 g_Wcomb_hi[PN * D_], g_Wcomb_lo[PN * D_];
__device__ float         g_bias_comb[PN];

// ---------------------------------------------------------------------------
// Helpers
// ---------------------------------------------------------------------------
__device__ __forceinline__ uint32_t smem_u32(const void* p) {
    uint32_t a;
    asm("{ .reg .u64 t; cvta.to.shared.u64 t, %1; cvt.u32.u64 %0, t; }" : "=r"(a) : "l"(p));
    return a;
}
// 128B-row swizzle: 16B-chunk index ^= (row & 7)
__device__ __forceinline__ uint32_t swz128(uint32_t off) { return off ^ ((off >> 3) & 0x70); }

__device__ __forceinline__ uint32_t pack2bf(float a, float b) {   // a -> low half
    __nv_bfloat162 t = __floats2bfloat162_rn(a, b);
    return *reinterpret_cast<uint32_t*>(&t);
}
__device__ __forceinline__ void bf_split(float x, float& hf, float& lf) {
    __nv_bfloat16 h = __float2bfloat16_rn(x);
    hf = __bfloat162float(h);
    lf = x - hf;
}

__device__ __forceinline__ void ldm_x4(uint32_t* r, uint32_t addr) {
    asm volatile("ldmatrix.sync.aligned.m8n8.x4.shared.b16 {%0,%1,%2,%3}, [%4];"
        : "=r"(r[0]), "=r"(r[1]), "=r"(r[2]), "=r"(r[3]) : "r"(addr));
}
__device__ __forceinline__ void mma_bf16(float* d, const uint32_t* a, const uint32_t* b) {
    asm volatile("mma.sync.aligned.m16n8k16.row.col.f32.bf16.bf16.f32 "
        "{%0,%1,%2,%3}, {%4,%5,%6,%7}, {%8,%9}, {%0,%1,%2,%3};"
        : "+f"(d[0]), "+f"(d[1]), "+f"(d[2]), "+f"(d[3])
        : "r"(a[0]), "r"(a[1]), "r"(a[2]), "r"(a[3]), "r"(b[0]), "r"(b[1]));
}

// ---------------------------------------------------------------------------
// bf16x3 GEMM via mma.sync: C[M,N] = A[M,256] @ (Bhi+Blo)[N,256]^T + bias
//   BM=128, BN=128, BK=64 bf16, 4 chunks, double-buffered SMEM, 8 warps,
//   warp tile 32x64. 3-term split: ah*bh + al*bh + ah*bl.
// SMEM per buffer: AH(16K) AL(16K) BH(16K) BL(16K) = 64KB; x2 = 128KB.
// ---------------------------------------------------------------------------
constexpr int SM_AH = 0;
constexpr int SM_AL = 16384;
constexpr int SM_BH = 32768;
constexpr int SM_BL = 49152;
constexpr int SM_BUFSZ = 65536;
constexpr int SMEM_GEMM = 2 * SM_BUFSZ;   // 131072

__global__ __launch_bounds__(256, 1)
void gemm_bf16x3(const float* __restrict__ A,
                 const __nv_bfloat16* __restrict__ Bhi,
                 const __nv_bfloat16* __restrict__ Blo,
                 const float* __restrict__ bias,
                 float* __restrict__ C, int N)
{
    extern __shared__ char smem[];
    const uint32_t sb = smem_u32(smem);
    const int tid  = threadIdx.x;
    const int bm   = blockIdx.x * 128;
    const int bn   = blockIdx.y * 128;
    const int w    = tid >> 5;
    const int lane = tid & 31;
    const int wm   = (w & 3) * 32;
    const int wn   = (w >> 2) * 64;

    // A staging mapping: row = tid>>1, half = tid&1 (32 floats along the row)
    const int arow  = tid >> 1;
    const int ahalf = tid & 1;
    const float* Abase = A + (size_t)(bm + arow) * 256 + ahalf * 32;

    float4 a_st[8];
    uint4  bh_st[4], bl_st[4];

    float acc[2][8][4];
    #pragma unroll
    for (int i = 0; i < 2; i++)
        #pragma unroll
        for (int j = 0; j < 8; j++)
            #pragma unroll
            for (int k = 0; k < 4; k++) acc[i][j][k] = 0.f;

    auto stage = [&](int c) {
        #pragma unroll
        for (int j = 0; j < 8; j++)
            a_st[j] = *(const float4*)(Abase + c * 64 + j * 4);
        #pragma unroll
        for (int i = 0; i < 4; i++) {
            int u = i * 256 + tid;
            int row = u >> 3, jj = u & 7;
            size_t gi = (size_t)(bn + row) * 256 + c * 64 + jj * 8;
            bh_st[i] = *(const uint4*)(Bhi + gi);
            bl_st[i] = *(const uint4*)(Blo + gi);
        }
    };
    auto cvtstore = [&](int buf) {
        char* bp = smem + buf * SM_BUFSZ;
        #pragma unroll
        for (int j = 0; j < 4; j++) {
            float4 v0 = a_st[2 * j], v1 = a_st[2 * j + 1];
            float h0,l0,h1,l1,h2,l2,h3,l3,h4,l4,h5,l5,h6,l6,h7,l7;
            bf_split(v0.x,h0,l0); bf_split(v0.y,h1,l1); bf_split(v0.z,h2,l2); bf_split(v0.w,h3,l3);
            bf_split(v1.x,h4,l4); bf_split(v1.y,h5,l5); bf_split(v1.z,h6,l6); bf_split(v1.w,h7,l7);
            uint4 hv = { pack2bf(h0,h1), pack2bf(h2,h3), pack2bf(h4,h5), pack2bf(h6,h7) };
            uint4 lv = { pack2bf(l0,l1), pack2bf(l2,l3), pack2bf(l4,l5), pack2bf(l6,l7) };
            uint32_t off = swz128((uint32_t)(arow * 128 + ahalf * 64 + j * 16));
            *(uint4*)(bp + SM_AH + off) = hv;
            *(uint4*)(bp + SM_AL + off) = lv;
        }
        #pragma unroll
        for (int i = 0; i < 4; i++) {
            int u = i * 256 + tid;
            int row = u >> 3, jj = u & 7;
            uint32_t off = swz128((uint32_t)(row * 128 + jj * 16));
            *(uint4*)(bp + SM_BH + off) = bh_st[i];
            *(uint4*)(bp + SM_BL + off) = bl_st[i];
        }
    };
    auto compute = [&](int buf) {
        const uint32_t ba = sb + buf * SM_BUFSZ;
        #pragma unroll
        for (int ks = 0; ks < 4; ks++) {
            const int kk = ks * 16;
            uint32_t ah[2][4], al_[2][4];
            #pragma unroll
            for (int mf = 0; mf < 2; mf++) {
                int m_loc = wm + mf * 16 + (lane & 15);
                int k_off = kk + (lane >> 4) * 8;
                uint32_t off = swz128((uint32_t)(m_loc * 128 + k_off * 2));
                ldm_x4(ah[mf],  ba + SM_AH + off);
                ldm_x4(al_[mf], ba + SM_AL + off);
            }
            uint32_t bh[8][2], bl[8][2];
            #pragma unroll
            for (int nf = 0; nf < 4; nf++) {
                int g = lane >> 3, r = lane & 7;
                int n_loc = wn + nf * 16 + ((g & 2) << 2) + r;  // +8 for g>=2
                int k_off = kk + (g & 1) * 8;
                uint32_t off = swz128((uint32_t)(n_loc * 128 + k_off * 2));
                uint32_t th[4], tl[4];
                ldm_x4(th, ba + SM_BH + off);
                ldm_x4(tl, ba + SM_BL + off);
                bh[2*nf][0]   = th[0]; bh[2*nf][1]   = th[1];
                bh[2*nf+1][0] = th[2]; bh[2*nf+1][1] = th[3];
                bl[2*nf][0]   = tl[0]; bl[2*nf][1]   = tl[1];
                bl[2*nf+1][0] = tl[2]; bl[2*nf+1][1] = tl[3];
            }
            #pragma unroll
            for (int mf = 0; mf < 2; mf++)
                #pragma unroll
                for (int n8 = 0; n8 < 8; n8++) {
                    mma_bf16(acc[mf][n8], ah[mf],  bh[n8]);
                    mma_bf16(acc[mf][n8], al_[mf], bh[n8]);
                    mma_bf16(acc[mf][n8], ah[mf],  bl[n8]);
                }
        }
    };

    stage(0);
    cvtstore(0);
    __syncthreads();

    for (int c = 0; c < 4; c++) {
        if (c < 3) stage(c + 1);
        compute(c & 1);
        __syncthreads();
        if (c < 3) {
            cvtstore((c + 1) & 1);
            __syncthreads();
        }
    }

    // Epilogue: direct global stores with bias (bias index = global column)
    #pragma unroll
    for (int mf = 0; mf < 2; mf++) {
        #pragma unroll
        for (int n8 = 0; n8 < 8; n8++) {
            int col = bn + wn + n8 * 8 + (lane & 3) * 2;
            int r0  = bm + wm + mf * 16 + (lane >> 2);
            float b0 = __ldg(bias + col);
            float b1 = __ldg(bias + col + 1);
            float2 v0 = { acc[mf][n8][0] + b0, acc[mf][n8][1] + b1 };
            float2 v1 = { acc[mf][n8][2] + b0, acc[mf][n8][3] + b1 };
            *(float2*)(C + (size_t)r0 * N + col)       = v0;
            *(float2*)(C + (size_t)(r0 + 8) * N + col) = v1;
        }
    }
}

// ---------------------------------------------------------------------------
// Weight prep: transpose to [N][K] and split into bf16 hi/lo
// ---------------------------------------------------------------------------
__global__ void prep_wsplit(const float* __restrict__ W,        // [256][256]
                            __nv_bfloat16* __restrict__ hi,
                            __nv_bfloat16* __restrict__ lo)
{
    int n = blockIdx.x, k = threadIdx.x;
    float x = W[(size_t)k * 256 + n];
    float hf, lf; bf_split(x, hf, lf);
    hi[(size_t)n * 256 + k] = __float2bfloat16_rn(hf);
    lo[(size_t)n * 256 + k] = __float2bfloat16_rn(lf);
}

__global__ void prep_wcomb(const float* __restrict__ W_off,     // [256][64]
                           const float* __restrict__ W_attn,    // [256][32]
                           const float* __restrict__ b_off,
                           const float* __restrict__ b_attn,
                           __nv_bfloat16* __restrict__ hi,
                           __nv_bfloat16* __restrict__ lo,
                           float* __restrict__ bias)
{
    int n = blockIdx.x, k = threadIdx.x;     // n < 128, k < 256
    float x = 0.f;
    if (n < 64)       x = W_off[(size_t)k * 64 + n];
    else if (n < 96)  x = W_attn[(size_t)k * 32 + (n - 64)];
    float hf, lf; bf_split(x, hf, lf);
    hi[(size_t)n * 256 + k] = __float2bfloat16_rn(hf);
    lo[(size_t)n * 256 + k] = __float2bfloat16_rn(lf);
    if (k == 0) bias[n] = (n < 64) ? b_off[n] : ((n < 96) ? b_attn[n - 64] : 0.f);
}

// ---------------------------------------------------------------------------
// Sample: softmax + bilinear gather; projections precomputed in g_proj.
// One CTA of 256 threads per (b,q). Warp h = head h, lane = channel.
// ---------------------------------------------------------------------------
__global__ __launch_bounds__(256)
void sample_kernel(const float* __restrict__ refpts)
{
    const int bq = blockIdx.x;
    const int b  = bq / Q_;
    const int t  = threadIdx.x;

    __shared__ float offs[NH * NP * 2];   // 64
    __shared__ float attn[NH * NP];       // 32

    if (t < 96) {
        float v = g_proj[(size_t)bq * PN + t];
        if (t < 64) offs[t] = v;
        else        attn[t - 64] = v;
    }
    __syncthreads();

    if (t < NH) {
        float m = attn[t * NP];
        #pragma unroll
        for (int p = 1; p < NP; p++) m = fmaxf(m, attn[t * NP + p]);
        float e[NP], s = 0.f;
        #pragma unroll
        for (int p = 0; p < NP; p++) { e[p] = __expf(attn[t * NP + p] - m); s += e[p]; }
        float inv = 1.f / s;
        #pragma unroll
        for (int p = 0; p < NP; p++) attn[t * NP + p] = e[p] * inv;
    }
    __syncthreads();

    const int h = t >> 5;
    const int d = t & 31;
    const float rx = refpts[(size_t)bq * 2 + 0];
    const float ry = refpts[(size_t)bq * 2 + 1];
    const float* vb = g_values + (size_t)b * HW * D_ + h * DH + d;

    float acc = 0.f;
    #pragma unroll
    for (int p = 0; p < NP; p++) {
        float lx = fminf(fmaxf(rx + offs[(h * NP + p) * 2 + 0], 0.f), 1.f);
        float ly = fminf(fmaxf(ry + offs[(h * NP + p) * 2 + 1], 0.f), 1.f);
        float sx = lx * (float)(Ww - 1);
        float sy = ly * (float)(Hh - 1);
        int x0 = min(max((int)floorf(sx), 0), Ww - 1);
        int y0 = min(max((int)floorf(sy), 0), Hh - 1);
        int x1 = min(x0 + 1, Ww - 1);
        int y1 = min(y0 + 1, Hh - 1);
        float wx1 = sx - (float)x0, wx0 = 1.f - wx1;
        float wy1 = sy - (float)y0, wy0 = 1.f - wy1;

        float g00 = vb[(size_t)(y0 * Ww + x0) * D_];
        float g01 = vb[(size_t)(y1 * Ww + x0) * D_];
        float g10 = vb[(size_t)(y0 * Ww + x1) * D_];
        float g11 = vb[(size_t)(y1 * Ww + x1) * D_];

        float bil = g00 * (wx0 * wy0) + g01 * (wx0 * wy1)
                  + g10 * (wx1 * wy0) + g11 * (wx1 * wy1);
        acc = fmaf(attn[h * NP + p], bil, acc);
    }
    g_result[(size_t)bq * D_ + t] = acc;
}

// ---------------------------------------------------------------------------
// kernel_launch
// Inputs: 0=query 1=reference_points 2=input_flatten 3=h 4=w
//   5=W_off 6=b_off 7=W_attn 8=b_attn 9=W_val 10=b_val 11=W_out 12=b_out
// ---------------------------------------------------------------------------
extern "C" void kernel_launch(void* const* d_in, const int* in_sizes, int n_in,
                              void* d_out, int out_size)
{
    const float* query    = (const float*)d_in[0];
    const float* refpts   = (const float*)d_in[1];
    const float* in_flat  = (const float*)d_in[2];
    const float* W_off    = (const float*)d_in[5];
    const float* b_off    = (const float*)d_in[6];
    const float* W_attn   = (const float*)d_in[7];
    const float* b_attn   = (const float*)d_in[8];
    const float* W_val    = (const float*)d_in[9];
    const float* b_val    = (const float*)d_in[10];
    const float* W_out    = (const float*)d_in[11];
    const float* b_out    = (const float*)d_in[12];
    float* out = (float*)d_out;

    float *values_p, *result_p, *proj_p, *biasc_p;
    __nv_bfloat16 *wvh, *wvl, *woh, *wol, *wch, *wcl;
    cudaGetSymbolAddress((void**)&values_p, g_values);
    cudaGetSymbolAddress((void**)&result_p, g_result);
    cudaGetSymbolAddress((void**)&proj_p,   g_proj);
    cudaGetSymbolAddress((void**)&biasc_p,  g_bias_comb);
    cudaGetSymbolAddress((void**)&wvh, g_WvalT_hi);
    cudaGetSymbolAddress((void**)&wvl, g_WvalT_lo);
    cudaGetSymbolAddress((void**)&woh, g_WoutT_hi);
    cudaGetSymbolAddress((void**)&wol, g_WoutT_lo);
    cudaGetSymbolAddress((void**)&wch, g_Wcomb_hi);
    cudaGetSymbolAddress((void**)&wcl, g_Wcomb_lo);

    cudaFuncSetAttribute(gemm_bf16x3, cudaFuncAttributeMaxDynamicSharedMemorySize, SMEM_GEMM);

    // 0) weight prep (tiny)
    prep_wsplit<<<256, 256>>>(W_val, wvh, wvl);
    prep_wsplit<<<256, 256>>>(W_out, woh, wol);
    prep_wcomb<<<128, 256>>>(W_off, W_attn, b_off, b_attn, wch, wcl, biasc_p);

    // 1) projections: g_proj[16384,128] = query @ Wcomb^T + bias_comb
    {
        dim3 grid(BQ / 128, 1);
        gemm_bf16x3<<<grid, 256, SMEM_GEMM>>>(query, wch, wcl, biasc_p, proj_p, PN);
    }

    // 2) values: g_values[80000,256] = input_flatten @ W_val + b_val
    {
        dim3 grid((B_ * HW) / 128, 2);
        gemm_bf16x3<<<grid, 256, SMEM_GEMM>>>(in_flat, wvh, wvl, b_val, values_p, D_);
    }

    // 3) softmax + bilinear sampling -> g_result[16384,256]
    sample_kernel<<<BQ, 256>>>(refpts);

    // 4) out = g_result @ W_out + b_out
    {
        dim3 grid(BQ / 128, 2);
        gemm_bf16x3<<<grid, 256, SMEM_GEMM>>>(result_p, woh, wol, b_out, out, D_);
    }
}